// round 1
// baseline (speedup 1.0000x reference)
#include <cuda_runtime.h>

#define B_ROWS 8192
#define KNUM   50
#define NKG    200000

// Scratch (static __device__ arrays — no runtime allocation)
__device__ float g_table[(size_t)NKG * 64];   // relu(kg @ Wkg + bkg), 51.2 MB
__device__ float g_h1[B_ROWS * 128];
__device__ float g_h2[B_ROWS * 512];
__device__ float g_h3[B_ROWS * 128];
__device__ float g_h4[B_ROWS * 64];
__device__ float g_know[B_ROWS * 64];

// ---------------------------------------------------------------------------
// Tiled SGEMM: C[M,N] = op(A @ B + bias), op = ReLU optional.
// FADD: A is replaced by (A + A2) elementwise during the A-tile load.
// BM=128, BN=64, BK=16, 256 threads, thread tile 8x4.
// Requires: N % 64 == 0, K % 16 == 0. M guarded.
// ---------------------------------------------------------------------------
template <bool RELU, bool FADD>
__global__ __launch_bounds__(256) void sgemm(const float* __restrict__ A,
                                             const float* __restrict__ A2,
                                             const float* __restrict__ Bm,
                                             const float* __restrict__ bias,
                                             float* __restrict__ C,
                                             int M, int N, int K)
{
    __shared__ float As[16][132];   // k-major, padded (float4-aligned rows)
    __shared__ float Bs[16][64];

    const int t  = threadIdx.x;
    const int tx = t & 15;          // 0..15 -> 4 cols each
    const int ty = t >> 4;          // 0..15 -> 8 rows each
    const int rowBase = blockIdx.x * 128;
    const int colBase = blockIdx.y * 64;

    // A tile load mapping: 128 rows x 16 k = 512 float4s; 2 per thread
    const int arow = t >> 2;        // 0..63 (and +64)
    const int ak   = (t & 3) * 4;   // k offset within tile
    // B tile load mapping: 16 rows x 64 = 256 float4s; 1 per thread
    const int brow = t >> 4;        // 0..15
    const int bcol = (t & 15) * 4;

    float acc[8][4];
#pragma unroll
    for (int i = 0; i < 8; i++)
#pragma unroll
        for (int j = 0; j < 4; j++) acc[i][j] = 0.f;

    for (int k0 = 0; k0 < K; k0 += 16) {
#pragma unroll
        for (int h = 0; h < 2; h++) {
            int r    = arow + h * 64;
            int grow = rowBase + r;
            float4 v = make_float4(0.f, 0.f, 0.f, 0.f);
            if (grow < M) {
                v = *(const float4*)(A + (size_t)grow * K + k0 + ak);
                if (FADD) {
                    float4 w = *(const float4*)(A2 + (size_t)grow * K + k0 + ak);
                    v.x += w.x; v.y += w.y; v.z += w.z; v.w += w.w;
                }
            }
            As[ak + 0][r] = v.x;
            As[ak + 1][r] = v.y;
            As[ak + 2][r] = v.z;
            As[ak + 3][r] = v.w;
        }
        *(float4*)(&Bs[brow][bcol]) =
            *(const float4*)(Bm + (size_t)(k0 + brow) * N + colBase + bcol);
        __syncthreads();

#pragma unroll
        for (int kk = 0; kk < 16; kk++) {
            float a[8], bb[4];
            *(float4*)(a)     = *(const float4*)(&As[kk][ty * 8]);
            *(float4*)(a + 4) = *(const float4*)(&As[kk][ty * 8 + 4]);
            *(float4*)(bb)    = *(const float4*)(&Bs[kk][tx * 4]);
#pragma unroll
            for (int i = 0; i < 8; i++)
#pragma unroll
                for (int j = 0; j < 4; j++)
                    acc[i][j] = fmaf(a[i], bb[j], acc[i][j]);
        }
        __syncthreads();
    }

    float4 bv = *(const float4*)(bias + colBase + tx * 4);
#pragma unroll
    for (int i = 0; i < 8; i++) {
        int grow = rowBase + ty * 8 + i;
        if (grow < M) {
            float4 o;
            o.x = acc[i][0] + bv.x;
            o.y = acc[i][1] + bv.y;
            o.z = acc[i][2] + bv.z;
            o.w = acc[i][3] + bv.w;
            if (RELU) {
                o.x = fmaxf(o.x, 0.f);
                o.y = fmaxf(o.y, 0.f);
                o.z = fmaxf(o.z, 0.f);
                o.w = fmaxf(o.w, 0.f);
            }
            *(float4*)(C + (size_t)grow * N + colBase + tx * 4) = o;
        }
    }
}

// ---------------------------------------------------------------------------
// Masked gather-sum over precomputed table: one warp per batch row.
// know[b][:] = sum_{k: mask=1} g_table[idx[b][k]][:]
// ---------------------------------------------------------------------------
__global__ __launch_bounds__(256) void gather_sum(const int* __restrict__ idx,
                                                  const int* __restrict__ mask)
{
    int w    = (blockIdx.x * 256 + threadIdx.x) >> 5;
    int lane = threadIdx.x & 31;
    if (w >= B_ROWS) return;

    const int* ib = idx  + w * KNUM;
    const int* mb = mask + w * KNUM;

    float2 acc = make_float2(0.f, 0.f);
#pragma unroll 2
    for (int k = 0; k < KNUM; k++) {
        int m = __ldg(&mb[k]);
        if (m) {
            int id   = __ldg(&ib[k]);
            float2 v = *(const float2*)(g_table + (size_t)id * 64 + lane * 2);
            acc.x += v.x;
            acc.y += v.y;
        }
    }
    *(float2*)(g_know + w * 64 + lane * 2) = acc;
}

// ---------------------------------------------------------------------------
extern "C" void kernel_launch(void* const* d_in, const int* in_sizes, int n_in,
                              void* d_out, int out_size)
{
    const float* x   = (const float*)d_in[0];
    const float* kg  = (const float*)d_in[1];
    const int*   idx = (const int*)d_in[2];
    const int*   msk = (const int*)d_in[3];
    const float* Wkg = (const float*)d_in[4];
    const float* bkg = (const float*)d_in[5];
    const float* W1a = (const float*)d_in[6];
    const float* b1a = (const float*)d_in[7];
    const float* W1b = (const float*)d_in[8];
    const float* b1b = (const float*)d_in[9];
    const float* W1c = (const float*)d_in[10];
    const float* b1c = (const float*)d_in[11];
    const float* W1d = (const float*)d_in[12];
    const float* b1d = (const float*)d_in[13];
    const float* W2  = (const float*)d_in[14];
    const float* b2  = (const float*)d_in[15];
    float* out = (float*)d_out;

    float *table, *h1, *h2, *h3, *h4, *know;
    cudaGetSymbolAddress((void**)&table, g_table);
    cudaGetSymbolAddress((void**)&h1, g_h1);
    cudaGetSymbolAddress((void**)&h2, g_h2);
    cudaGetSymbolAddress((void**)&h3, g_h3);
    cudaGetSymbolAddress((void**)&h4, g_h4);
    cudaGetSymbolAddress((void**)&know, g_know);

    dim3 blk(256);

    // 1) knowledge table: T = relu(kg @ Wkg + bkg)   [200000, 64]
    sgemm<true, false><<<dim3((NKG + 127) / 128, 1), blk>>>(
        kg, nullptr, Wkg, bkg, table, NKG, 64, 64);

    // 2) masked gather-sum over table (runs while table is L2-hot)
    gather_sum<<<(B_ROWS * 32) / 256, blk>>>(idx, msk);

    // 3) dense MLP chain
    sgemm<true, false><<<dim3(64, 2), blk>>>(x,  nullptr, W1a, b1a, h1, B_ROWS, 128, 512);
    sgemm<true, false><<<dim3(64, 8), blk>>>(h1, nullptr, W1b, b1b, h2, B_ROWS, 512, 128);
    sgemm<true, false><<<dim3(64, 2), blk>>>(h2, nullptr, W1c, b1c, h3, B_ROWS, 128, 512);
    sgemm<true, false><<<dim3(64, 1), blk>>>(h3, nullptr, W1d, b1d, h4, B_ROWS, 64, 128);

    // 4) out = (knowledge + h4) @ W2 + b2  (add fused into A-tile load)
    sgemm<false, true><<<dim3(64, 16), blk>>>(h4, know, W2, b2, out, B_ROWS, 1024, 64);
}

// round 2
// speedup vs baseline: 2.3913x; 2.3913x over previous
#include <cuda_runtime.h>

#define B_ROWS 8192
#define KNUM   50
#define NKG    200000

// Scratch (static __device__ arrays — no runtime allocation)
__device__ float g_table[(size_t)NKG * 64];   // relu(kg @ Wkg + bkg)
__device__ float g_h1[B_ROWS * 128];
__device__ float g_h2[B_ROWS * 512];
__device__ float g_h3[B_ROWS * 128];
__device__ float g_h4[B_ROWS * 64];
__device__ float g_know[B_ROWS * 64];

__device__ __forceinline__ unsigned f2tf(float f) {
    unsigned u;
    asm("cvt.rna.tf32.f32 %0, %1;" : "=r"(u) : "f"(f));
    return u;
}

__device__ __forceinline__ void mma8(float* c, const unsigned* a, const unsigned* b) {
    asm volatile(
        "mma.sync.aligned.m16n8k8.row.col.f32.tf32.tf32.f32 "
        "{%0,%1,%2,%3}, {%4,%5,%6,%7}, {%8,%9}, {%0,%1,%2,%3};"
        : "+f"(c[0]), "+f"(c[1]), "+f"(c[2]), "+f"(c[3])
        : "r"(a[0]), "r"(a[1]), "r"(a[2]), "r"(a[3]), "r"(b[0]), "r"(b[1]));
}

// ---------------------------------------------------------------------------
// TF32 tensor-core GEMM: C[M,N] = op(A @ W + bias), RELU optional,
// FADD: A := A + A2 fused into staging.
// BM=128, BN=64, BK=32, 256 threads (8 warps: 4 along M x 2 along N).
// Each warp: 32x32 = 2x4 tiles of m16n8k8.
// Requires N % 64 == 0, K % 32 == 0; M guarded.
// SMEM holds pre-permuted TF32 fragments:
//   As[ks(4)][mtile(8)][slot(4)][lane(32)]   (16 KB)
//   Bs[ks(4)][ntile(8)][slot(2)][lane(32)]   ( 8 KB)
// All mainloop LDS are conflict-free LDS.32; A staging is STS.128.
// ---------------------------------------------------------------------------
template <bool RELU, bool FADD>
__global__ __launch_bounds__(256) void tgemm(const float* __restrict__ A,
                                             const float* __restrict__ A2,
                                             const float* __restrict__ W,
                                             const float* __restrict__ bias,
                                             float* __restrict__ C,
                                             int M, int N, int K)
{
    __shared__ unsigned As[4 * 8 * 4 * 32];
    __shared__ unsigned Bs[4 * 8 * 2 * 32];

    const int t      = threadIdx.x;
    const int lane   = t & 31;
    const int wid    = t >> 5;
    const int warp_m = wid & 3;   // 0..3
    const int warp_n = wid >> 2;  // 0..1
    const int rowBase = blockIdx.x * 128;
    const int colBase = blockIdx.y * 64;

    float a_pre[4][4];   // 4 float4s of A tile per thread
    float b_pre[2][4];   // 2 float4s of W tile per thread

    float acc[2][4][4];
#pragma unroll
    for (int i = 0; i < 2; i++)
#pragma unroll
        for (int j = 0; j < 4; j++)
#pragma unroll
            for (int c = 0; c < 4; c++) acc[i][j][c] = 0.f;

    auto loadTile = [&](int k0) {
#pragma unroll
        for (int p = 0; p < 4; p++) {            // A: v in [0,1024)
            int v   = t * 4 + p;
            int row = v >> 3;
            int col = (v & 7) * 4;
            int grow = rowBase + row;
            float4 x = make_float4(0.f, 0.f, 0.f, 0.f);
            if (grow < M) {
                x = *(const float4*)(A + (size_t)grow * K + k0 + col);
                if (FADD) {
                    float4 y = *(const float4*)(A2 + (size_t)grow * K + k0 + col);
                    x.x += y.x; x.y += y.y; x.z += y.z; x.w += y.w;
                }
            }
            a_pre[p][0] = x.x; a_pre[p][1] = x.y; a_pre[p][2] = x.z; a_pre[p][3] = x.w;
        }
#pragma unroll
        for (int p = 0; p < 2; p++) {            // B: v in [0,512)
            int v  = t * 2 + p;
            int kk = v >> 4;
            int n0 = (v & 15) * 4;
            float4 x = *(const float4*)(W + (size_t)(k0 + kk) * N + colBase + n0);
            b_pre[p][0] = x.x; b_pre[p][1] = x.y; b_pre[p][2] = x.z; b_pre[p][3] = x.w;
        }
    };

    auto stage = [&]() {
#pragma unroll
        for (int p = 0; p < 4; p++) {
            int v   = t * 4 + p;
            int row = v >> 3;
            int col = (v & 7) * 4;
            int ks    = col >> 3;
            int mtile = row >> 4;
            int slot  = ((row & 15) >> 3) + ((col & 4) >> 1);
            int off   = ((ks * 8 + mtile) * 4 + slot) * 32 + (row & 7) * 4;
            uint4 w;
            w.x = f2tf(a_pre[p][0]); w.y = f2tf(a_pre[p][1]);
            w.z = f2tf(a_pre[p][2]); w.w = f2tf(a_pre[p][3]);
            *(uint4*)(As + off) = w;
        }
#pragma unroll
        for (int p = 0; p < 2; p++) {
            int v  = t * 2 + p;
            int kk = v >> 4;
            int n0 = (v & 15) * 4;
            int ks    = kk >> 3;
            int slotB = (kk & 7) >> 2;
            int ntile = n0 >> 3;
            int base  = ((ks * 8 + ntile) * 2 + slotB) * 32 + (kk & 3);
#pragma unroll
            for (int e = 0; e < 4; e++)
                Bs[base + ((n0 & 7) + e) * 4] = f2tf(b_pre[p][e]);
        }
    };

    loadTile(0);
    stage();
    __syncthreads();

    for (int k0 = 0;;) {
        int knext = k0 + 32;
        bool more = knext < K;
        if (more) loadTile(knext);     // prefetch next tile into registers

#pragma unroll
        for (int ks = 0; ks < 4; ks++) {
            unsigned af[2][4], bf[4][2];
#pragma unroll
            for (int i = 0; i < 2; i++) {
                int mt = warp_m * 2 + i;
                int o  = ((ks * 8 + mt) * 4) * 32 + lane;
                af[i][0] = As[o];
                af[i][1] = As[o + 32];
                af[i][2] = As[o + 64];
                af[i][3] = As[o + 96];
            }
#pragma unroll
            for (int j = 0; j < 4; j++) {
                int nt = warp_n * 4 + j;
                int o  = ((ks * 8 + nt) * 2) * 32 + lane;
                bf[j][0] = Bs[o];
                bf[j][1] = Bs[o + 32];
            }
#pragma unroll
            for (int i = 0; i < 2; i++)
#pragma unroll
                for (int j = 0; j < 4; j++)
                    mma8(acc[i][j], af[i], bf[j]);
        }

        if (!more) break;
        __syncthreads();
        stage();
        __syncthreads();
        k0 = knext;
    }

    // Epilogue: c0,c1 at (gid, tig*2 + {0,1}); c2,c3 at row+8.
    const int gid = lane >> 2;
    const int tig = lane & 3;
#pragma unroll
    for (int i = 0; i < 2; i++) {
        int row0 = rowBase + warp_m * 32 + i * 16 + gid;
#pragma unroll
        for (int j = 0; j < 4; j++) {
            int col = colBase + warp_n * 32 + j * 8 + tig * 2;
            float2 bv = *(const float2*)(bias + col);
            if (row0 < M) {
                float2 o = make_float2(acc[i][j][0] + bv.x, acc[i][j][1] + bv.y);
                if (RELU) { o.x = fmaxf(o.x, 0.f); o.y = fmaxf(o.y, 0.f); }
                *(float2*)(C + (size_t)row0 * N + col) = o;
            }
            if (row0 + 8 < M) {
                float2 o = make_float2(acc[i][j][2] + bv.x, acc[i][j][3] + bv.y);
                if (RELU) { o.x = fmaxf(o.x, 0.f); o.y = fmaxf(o.y, 0.f); }
                *(float2*)(C + (size_t)(row0 + 8) * N + col) = o;
            }
        }
    }
}

// ---------------------------------------------------------------------------
// Masked gather-sum over precomputed table: one warp per batch row.
// know[b][:] = sum_{k: mask=1} g_table[idx[b][k]][:]
// ---------------------------------------------------------------------------
__global__ __launch_bounds__(256) void gather_sum(const int* __restrict__ idx,
                                                  const int* __restrict__ mask)
{
    int w    = (blockIdx.x * 256 + threadIdx.x) >> 5;
    int lane = threadIdx.x & 31;
    if (w >= B_ROWS) return;

    const int* ib = idx  + w * KNUM;
    const int* mb = mask + w * KNUM;

    float2 acc = make_float2(0.f, 0.f);
#pragma unroll 2
    for (int k = 0; k < KNUM; k++) {
        int m = __ldg(&mb[k]);
        if (m) {
            int id   = __ldg(&ib[k]);
            float2 v = *(const float2*)(g_table + (size_t)id * 64 + lane * 2);
            acc.x += v.x;
            acc.y += v.y;
        }
    }
    *(float2*)(g_know + w * 64 + lane * 2) = acc;
}

// ---------------------------------------------------------------------------
extern "C" void kernel_launch(void* const* d_in, const int* in_sizes, int n_in,
                              void* d_out, int out_size)
{
    const float* x   = (const float*)d_in[0];
    const float* kg  = (const float*)d_in[1];
    const int*   idx = (const int*)d_in[2];
    const int*   msk = (const int*)d_in[3];
    const float* Wkg = (const float*)d_in[4];
    const float* bkg = (const float*)d_in[5];
    const float* W1a = (const float*)d_in[6];
    const float* b1a = (const float*)d_in[7];
    const float* W1b = (const float*)d_in[8];
    const float* b1b = (const float*)d_in[9];
    const float* W1c = (const float*)d_in[10];
    const float* b1c = (const float*)d_in[11];
    const float* W1d = (const float*)d_in[12];
    const float* b1d = (const float*)d_in[13];
    const float* W2  = (const float*)d_in[14];
    const float* b2  = (const float*)d_in[15];
    float* out = (float*)d_out;

    float *table, *h1, *h2, *h3, *h4, *know;
    cudaGetSymbolAddress((void**)&table, g_table);
    cudaGetSymbolAddress((void**)&h1, g_h1);
    cudaGetSymbolAddress((void**)&h2, g_h2);
    cudaGetSymbolAddress((void**)&h3, g_h3);
    cudaGetSymbolAddress((void**)&h4, g_h4);
    cudaGetSymbolAddress((void**)&know, g_know);

    dim3 blk(256);

    // 1) knowledge table: T = relu(kg @ Wkg + bkg)   [200000, 64]
    tgemm<true, false><<<dim3((NKG + 127) / 128, 1), blk>>>(
        kg, nullptr, Wkg, bkg, table, NKG, 64, 64);

    // 2) masked gather-sum over table (L2-hot)
    gather_sum<<<(B_ROWS * 32) / 256, blk>>>(idx, msk);

    // 3) dense MLP chain
    tgemm<true, false><<<dim3(64, 2), blk>>>(x,  nullptr, W1a, b1a, h1, B_ROWS, 128, 512);
    tgemm<true, false><<<dim3(64, 8), blk>>>(h1, nullptr, W1b, b1b, h2, B_ROWS, 512, 128);
    tgemm<true, false><<<dim3(64, 2), blk>>>(h2, nullptr, W1c, b1c, h3, B_ROWS, 128, 512);
    tgemm<true, false><<<dim3(64, 1), blk>>>(h3, nullptr, W1d, b1d, h4, B_ROWS, 64, 128);

    // 4) out = (knowledge + h4) @ W2 + b2  (add fused into A-tile staging)
    tgemm<false, true><<<dim3(64, 16), blk>>>(h4, know, W2, b2, out, B_ROWS, 1024, 64);
}

// round 3
// speedup vs baseline: 3.5337x; 1.4777x over previous
#include <cuda_runtime.h>

#define B_ROWS 8192
#define KNUM   50
#define NKG    200000

// Pipeline geometry
#define BM 128
#define BN 64
#define BK 32
#define STAGES 3
#define A_STRIDE 40              // 32 + 8 pad (words) -> conflict-free frag loads
#define B_STRIDE 72              // 64 + 8 pad (words)
#define A_TILE_W (BM * A_STRIDE) // 5120 words
#define B_TILE_W (BK * B_STRIDE) // 2304 words
#define STAGE_W  (A_TILE_W + B_TILE_W)
#define SMEM_BYTES (STAGES * STAGE_W * 4)

// Scratch (static __device__ arrays — no runtime allocation)
__device__ float g_table[(size_t)NKG * 64];
__device__ float g_h1[B_ROWS * 128];
__device__ float g_h2[B_ROWS * 512];
__device__ float g_h3[B_ROWS * 128];
__device__ float g_h4[B_ROWS * 64];
__device__ float g_know[B_ROWS * 64];

__device__ __forceinline__ unsigned f2tf(float f) {
    unsigned u;
    asm("cvt.rna.tf32.f32 %0, %1;" : "=r"(u) : "f"(f));
    return u;
}

__device__ __forceinline__ void mma8(float* c, const unsigned* a, const unsigned* b) {
    asm volatile(
        "mma.sync.aligned.m16n8k8.row.col.f32.tf32.tf32.f32 "
        "{%0,%1,%2,%3}, {%4,%5,%6,%7}, {%8,%9}, {%0,%1,%2,%3};"
        : "+f"(c[0]), "+f"(c[1]), "+f"(c[2]), "+f"(c[3])
        : "r"(a[0]), "r"(a[1]), "r"(a[2]), "r"(a[3]), "r"(b[0]), "r"(b[1]));
}

__device__ __forceinline__ void cpasync16(unsigned dst, const void* src) {
    asm volatile("cp.async.cg.shared.global [%0], [%1], 16;" :: "r"(dst), "l"(src));
}
__device__ __forceinline__ void cpcommit() {
    asm volatile("cp.async.commit_group;" ::: "memory");
}
__device__ __forceinline__ void cpwait1() {
    asm volatile("cp.async.wait_group 1;" ::: "memory");
}

// ---------------------------------------------------------------------------
// TF32 tensor-core GEMM, cp.async 3-stage pipeline.
// C[M,N] = op(A @ W + bias), RELU optional; EPIADD: C += addv after ReLU.
// BM=128, BN=64, BK=32, 256 threads (8 warps: 4 along M x 2 along N),
// warp tile 32x32 as 2x4 m16n8k8. Raw row-major smem tiles, padded strides,
// fragments pulled with conflict-free LDS.32, tf32 cvt at read time.
// Requires N % 64 == 0, K % 32 == 0 (and K >= 64); M guarded.
// ---------------------------------------------------------------------------
template <bool RELU, bool EPIADD>
__global__ __launch_bounds__(256) void tgemm(const float* __restrict__ A,
                                             const float* __restrict__ W,
                                             const float* __restrict__ bias,
                                             const float* __restrict__ addv,
                                             float* __restrict__ C,
                                             int M, int N, int K)
{
    extern __shared__ float sm[];
    const unsigned smBase = (unsigned)__cvta_generic_to_shared(sm);

    const int t      = threadIdx.x;
    const int lane   = t & 31;
    const int wid    = t >> 5;
    const int warp_m = wid & 3;
    const int warp_n = wid >> 2;
    const int gid    = lane >> 2;
    const int tig    = lane & 3;
    const int rowBase = blockIdx.x * BM;
    const int colBase = blockIdx.y * BN;

    // Per-thread load mapping (fixed across tiles)
    // A: 1024 float4s -> 4/thread: v = t + p*256, row = v>>3, seg = v&7
    // B:  512 float4s -> 2/thread: v = t + p*256, kk  = v>>4, seg = v&15
    const int ntiles = K / BK;

    auto issueTile = [&](int tile, int stage) {
        const int k0 = tile * BK;
        const unsigned sOff = smBase + stage * (STAGE_W * 4);
#pragma unroll
        for (int p = 0; p < 4; p++) {
            int v = t + p * 256;
            int row = v >> 3, seg = v & 7;
            if (rowBase + row < M) {
                unsigned dst = sOff + (row * A_STRIDE + seg * 4) * 4;
                cpasync16(dst, A + (size_t)(rowBase + row) * K + k0 + seg * 4);
            }
        }
#pragma unroll
        for (int p = 0; p < 2; p++) {
            int v = t + p * 256;
            int kk = v >> 4, seg = v & 15;
            unsigned dst = sOff + (A_TILE_W + kk * B_STRIDE + seg * 4) * 4;
            cpasync16(dst, W + (size_t)(k0 + kk) * N + colBase + seg * 4);
        }
        cpcommit();
    };

    float acc[2][4][4];
#pragma unroll
    for (int i = 0; i < 2; i++)
#pragma unroll
        for (int j = 0; j < 4; j++)
#pragma unroll
            for (int c = 0; c < 4; c++) acc[i][j][c] = 0.f;

    // Prologue: fill STAGES-1 = 2 stages
    issueTile(0, 0);
    issueTile(1, 1);

    for (int i = 0; i < ntiles; i++) {
        cpwait1();             // tile i complete (groups retire in order)
        __syncthreads();       // all warps past previous compute + see tile i

        int nxt = i + STAGES - 1;
        if (nxt < ntiles) issueTile(nxt, nxt % STAGES);
        else cpcommit();       // keep group count consistent for cpwait1

        const float* sA = sm + (i % STAGES) * STAGE_W;
        const float* sB = sA + A_TILE_W;

#pragma unroll
        for (int ks = 0; ks < 4; ks++) {
            unsigned af[2][4], bf[4][2];
#pragma unroll
            for (int i2 = 0; i2 < 2; i2++) {
                int mt = warp_m * 2 + i2;
                const float* p = sA + (mt * 16 + gid) * A_STRIDE + ks * 8 + tig;
                af[i2][0] = f2tf(p[0]);
                af[i2][1] = f2tf(p[8 * A_STRIDE]);
                af[i2][2] = f2tf(p[4]);
                af[i2][3] = f2tf(p[8 * A_STRIDE + 4]);
            }
#pragma unroll
            for (int j = 0; j < 4; j++) {
                int nt = warp_n * 4 + j;
                const float* p = sB + (ks * 8 + tig) * B_STRIDE + nt * 8 + gid;
                bf[j][0] = f2tf(p[0]);
                bf[j][1] = f2tf(p[4 * B_STRIDE]);
            }
#pragma unroll
            for (int i2 = 0; i2 < 2; i2++)
#pragma unroll
                for (int j = 0; j < 4; j++)
                    mma8(acc[i2][j], af[i2], bf[j]);
        }
    }

    // Epilogue: c0,c1 at (row, tig*2+{0,1}); c2,c3 at row+8.
#pragma unroll
    for (int i = 0; i < 2; i++) {
        int row0 = rowBase + warp_m * 32 + i * 16 + gid;
#pragma unroll
        for (int j = 0; j < 4; j++) {
            int col = colBase + warp_n * 32 + j * 8 + tig * 2;
            float2 bv = *(const float2*)(bias + col);
            if (row0 < M) {
                float2 o = make_float2(acc[i][j][0] + bv.x, acc[i][j][1] + bv.y);
                if (RELU) { o.x = fmaxf(o.x, 0.f); o.y = fmaxf(o.y, 0.f); }
                if (EPIADD) {
                    float2 av = *(const float2*)(addv + (size_t)row0 * N + col);
                    o.x += av.x; o.y += av.y;
                }
                *(float2*)(C + (size_t)row0 * N + col) = o;
            }
            if (row0 + 8 < M) {
                float2 o = make_float2(acc[i][j][2] + bv.x, acc[i][j][3] + bv.y);
                if (RELU) { o.x = fmaxf(o.x, 0.f); o.y = fmaxf(o.y, 0.f); }
                if (EPIADD) {
                    float2 av = *(const float2*)(addv + (size_t)(row0 + 8) * N + col);
                    o.x += av.x; o.y += av.y;
                }
                *(float2*)(C + (size_t)(row0 + 8) * N + col) = o;
            }
        }
    }
}

// ---------------------------------------------------------------------------
// Masked gather-sum over precomputed table: one warp per batch row.
// ---------------------------------------------------------------------------
__global__ __launch_bounds__(256) void gather_sum(const int* __restrict__ idx,
                                                  const int* __restrict__ mask)
{
    int w    = (blockIdx.x * 256 + threadIdx.x) >> 5;
    int lane = threadIdx.x & 31;
    if (w >= B_ROWS) return;

    const int* ib = idx  + w * KNUM;
    const int* mb = mask + w * KNUM;

    float2 acc = make_float2(0.f, 0.f);
#pragma unroll 5
    for (int k = 0; k < KNUM; k++) {
        int m = __ldg(&mb[k]);
        if (m) {
            int id   = __ldg(&ib[k]);
            float2 v = *(const float2*)(g_table + (size_t)id * 64 + lane * 2);
            acc.x += v.x;
            acc.y += v.y;
        }
    }
    *(float2*)(g_know + w * 64 + lane * 2) = acc;
}

// ---------------------------------------------------------------------------
extern "C" void kernel_launch(void* const* d_in, const int* in_sizes, int n_in,
                              void* d_out, int out_size)
{
    const float* x   = (const float*)d_in[0];
    const float* kg  = (const float*)d_in[1];
    const int*   idx = (const int*)d_in[2];
    const int*   msk = (const int*)d_in[3];
    const float* Wkg = (const float*)d_in[4];
    const float* bkg = (const float*)d_in[5];
    const float* W1a = (const float*)d_in[6];
    const float* b1a = (const float*)d_in[7];
    const float* W1b = (const float*)d_in[8];
    const float* b1b = (const float*)d_in[9];
    const float* W1c = (const float*)d_in[10];
    const float* b1c = (const float*)d_in[11];
    const float* W1d = (const float*)d_in[12];
    const float* b1d = (const float*)d_in[13];
    const float* W2  = (const float*)d_in[14];
    const float* b2  = (const float*)d_in[15];
    float* out = (float*)d_out;

    float *table, *h1, *h2, *h3, *h4, *know;
    cudaGetSymbolAddress((void**)&table, g_table);
    cudaGetSymbolAddress((void**)&h1, g_h1);
    cudaGetSymbolAddress((void**)&h2, g_h2);
    cudaGetSymbolAddress((void**)&h3, g_h3);
    cudaGetSymbolAddress((void**)&h4, g_h4);
    cudaGetSymbolAddress((void**)&know, g_know);

    cudaFuncSetAttribute(tgemm<true, false>,
                         cudaFuncAttributeMaxDynamicSharedMemorySize, SMEM_BYTES);
    cudaFuncSetAttribute(tgemm<true, true>,
                         cudaFuncAttributeMaxDynamicSharedMemorySize, SMEM_BYTES);
    cudaFuncSetAttribute(tgemm<false, false>,
                         cudaFuncAttributeMaxDynamicSharedMemorySize, SMEM_BYTES);

    dim3 blk(256);

    // 1) knowledge table: T = relu(kg @ Wkg + bkg)   [200000, 64]
    tgemm<true, false><<<dim3((NKG + BM - 1) / BM, 1), blk, SMEM_BYTES>>>(
        kg, Wkg, bkg, nullptr, table, NKG, 64, 64);

    // 2) masked gather-sum over table (L2-hot)
    gather_sum<<<(B_ROWS * 32) / 256, blk>>>(idx, msk);

    // 3) dense MLP chain
    tgemm<true, false><<<dim3(64, 2), blk, SMEM_BYTES>>>(x,  W1a, b1a, nullptr, h1, B_ROWS, 128, 512);
    tgemm<true, false><<<dim3(64, 8), blk, SMEM_BYTES>>>(h1, W1b, b1b, nullptr, h2, B_ROWS, 512, 128);
    tgemm<true, false><<<dim3(64, 2), blk, SMEM_BYTES>>>(h2, W1c, b1c, nullptr, h3, B_ROWS, 128, 512);
    // h4 = relu(h3 @ W1d + b1d) + knowledge   (add fused in epilogue)
    tgemm<true, true><<<dim3(64, 1), blk, SMEM_BYTES>>>(h3, W1d, b1d, know, h4, B_ROWS, 64, 128);

    // 4) out = h4 @ W2 + b2
    tgemm<false, false><<<dim3(64, 16), blk, SMEM_BYTES>>>(h4, W2, b2, nullptr, out, B_ROWS, 1024, 64);
}